// round 16
// baseline (speedup 1.0000x reference)
#include <cuda_runtime.h>
#include <cuda_fp16.h>
#include <stdint.h>
#include <math.h>

#define D_MODEL     1024
#define EXPERT_DIM  2048
#define NUM_EXPERTS 16
#define SEQ_LEN     2048
#define BATCH       2
#define NTOK        (SEQ_LEN*BATCH)      // 4096 tokens
#define NASSIGN     (NTOK*2)             // 8192 (token, k) assignments

// ---- scratch (static __device__: no allocations allowed) ----
__device__ __half g_Xh[(size_t)NTOK * D_MODEL];                        // 8 MB
__device__ __half g_Hh[(size_t)NASSIGN * EXPERT_DIM];                  // 32 MB
__device__ __half g_W1h[(size_t)NUM_EXPERTS * D_MODEL * EXPERT_DIM];   // 64 MB
__device__ __half g_W2h[(size_t)NUM_EXPERTS * EXPERT_DIM * D_MODEL];   // 64 MB
__device__ int   g_cnt[NUM_EXPERTS];
__device__ int   g_list[NUM_EXPERTS * NTOK];
__device__ float g_rw[NASSIGN];

// ---- prep_misc: zero out, zero counters, cvt x -> fp16 ----
__global__ void prep_misc_kernel(const float* __restrict__ x,
                                 float4* __restrict__ out, int n4, int n8x) {
    int i = blockIdx.x * blockDim.x + threadIdx.x;
    if (i < n4) out[i] = make_float4(0.f, 0.f, 0.f, 0.f);
    if (i < n8x) {
        const float4* in4 = (const float4*)x;
        float4 a = in4[2 * i], b = in4[2 * i + 1];
        __half2 h[4];
        h[0] = __floats2half2_rn(a.x, a.y);
        h[1] = __floats2half2_rn(a.z, a.w);
        h[2] = __floats2half2_rn(b.x, b.y);
        h[3] = __floats2half2_rn(b.z, b.w);
        *(uint4*)(g_Xh + 8 * (size_t)i) = *(uint4*)h;
    }
    if (i < NUM_EXPERTS) g_cnt[i] = 0;
}

// ---- cvt one weight tensor fp32 -> fp16 ----
__global__ void cvt_w_kernel(const float* __restrict__ W, __half* __restrict__ Wh, int n8) {
    int i = blockIdx.x * blockDim.x + threadIdx.x;
    if (i >= n8) return;
    const float4* in4 = (const float4*)W;
    float4 a = in4[2 * i], b = in4[2 * i + 1];
    __half2 h[4];
    h[0] = __floats2half2_rn(a.x, a.y);
    h[1] = __floats2half2_rn(a.z, a.w);
    h[2] = __floats2half2_rn(b.x, b.y);
    h[3] = __floats2half2_rn(b.z, b.w);
    *(uint4*)(Wh + 8 * (size_t)i) = *(uint4*)h;
}

// ---- gating: one warp per token (fp32, raw x) ----
__global__ void gate_kernel(const float* __restrict__ x,
                            const float* __restrict__ Wg,
                            const float* __restrict__ bg,
                            const float* __restrict__ bias) {
    int gwarp = (blockIdx.x * blockDim.x + threadIdx.x) >> 5;
    int lane  = threadIdx.x & 31;
    if (gwarp >= NTOK) return;
    const float* xr = x + (size_t)gwarp * D_MODEL;

    float xv[32];
    #pragma unroll
    for (int j = 0; j < 32; j++) xv[j] = xr[lane + 32 * j];

    float logits[NUM_EXPERTS];
    #pragma unroll
    for (int e = 0; e < NUM_EXPERTS; e++) {
        float s = 0.f;
        #pragma unroll
        for (int j = 0; j < 32; j++)
            s += xv[j] * Wg[(size_t)(lane + 32 * j) * NUM_EXPERTS + e];
        #pragma unroll
        for (int o = 16; o; o >>= 1) s += __shfl_xor_sync(0xffffffffu, s, o);
        logits[e] = s + bg[e] + bias[e];
    }

    if (lane == 0) {
        int e0 = 0; float v0 = logits[0];
        #pragma unroll
        for (int e = 1; e < NUM_EXPERTS; e++)
            if (logits[e] > v0) { v0 = logits[e]; e0 = e; }
        int e1 = -1; float v1 = -1e30f;
        #pragma unroll
        for (int e = 0; e < NUM_EXPERTS; e++)
            if (e != e0 && logits[e] > v1) { v1 = logits[e]; e1 = e; }

        float ew1 = __expf(v1 - v0);
        float inv = 1.f / (1.f + ew1);
        g_rw[gwarp * 2 + 0] = inv;
        g_rw[gwarp * 2 + 1] = ew1 * inv;
        int p0 = atomicAdd(&g_cnt[e0], 1);
        g_list[e0 * NTOK + p0] = gwarp * 2 + 0;
        int p1 = atomicAdd(&g_cnt[e1], 1);
        g_list[e1 * NTOK + p1] = gwarp * 2 + 1;
    }
}

// ================= mma / ldmatrix / cp.async helpers =================
__device__ __forceinline__ void mma_f16(float* d, const uint32_t* a, const uint32_t* b) {
    asm volatile(
        "mma.sync.aligned.m16n8k16.row.col.f32.f16.f16.f32 "
        "{%0,%1,%2,%3}, {%4,%5,%6,%7}, {%8,%9}, {%0,%1,%2,%3};\n"
        : "+f"(d[0]), "+f"(d[1]), "+f"(d[2]), "+f"(d[3])
        : "r"(a[0]), "r"(a[1]), "r"(a[2]), "r"(a[3]), "r"(b[0]), "r"(b[1]));
}
__device__ __forceinline__ void ldsm4(uint32_t* r, uint32_t a) {
    asm volatile("ldmatrix.sync.aligned.m8n8.x4.shared.b16 {%0,%1,%2,%3}, [%4];"
        : "=r"(r[0]), "=r"(r[1]), "=r"(r[2]), "=r"(r[3]) : "r"(a));
}
__device__ __forceinline__ void ldsm4t(uint32_t* r, uint32_t a) {
    asm volatile("ldmatrix.sync.aligned.m8n8.x4.trans.shared.b16 {%0,%1,%2,%3}, [%4];"
        : "=r"(r[0]), "=r"(r[1]), "=r"(r[2]), "=r"(r[3]) : "r"(a));
}
__device__ __forceinline__ void cpa16(uint32_t dst, const void* src) {
    asm volatile("cp.async.cg.shared.global [%0], [%1], 16;" :: "r"(dst), "l"(src));
}
#define CPA_COMMIT() asm volatile("cp.async.commit_group;" ::: "memory")
#define CPA_WAIT(n)  asm volatile("cp.async.wait_group %0;" :: "n"(n) : "memory")

// smem layout (5-stage ring, k16/stage, block tile 128m x 256n, fp16):
#define ASTRB     48
#define BSTRB     528
#define STG       5
#define SM_A      512
#define SM_ASTG   (128 * ASTRB)              // 6144
#define SM_B      (SM_A + STG * SM_ASTG)     // 31232
#define SM_BSTG   (16 * BSTRB)               // 8448
#define SM_TOTAL  (SM_B + STG * SM_BSTG)     // 73472

// 512 threads = 16 warps (4m x 4n), warp tile 32x64, 1 CTA/SM. (round-8 proven)
template<int K, int N, int KSPLIT, bool FC1>
__global__ __launch_bounds__(512, 1)
void expert_mma(const __half* __restrict__ Wbase,
                const float* __restrict__ BiasBase,
                float* __restrict__ out) {
    extern __shared__ char smem[];
    const int z    = blockIdx.z;
    const int e    = z / KSPLIT;
    const int ks   = z % KSPLIT;
    const int KS   = K / KSPLIT;
    const int koff = ks * KS;
    const int cnt  = g_cnt[e];
    const int m0   = blockIdx.y * 128;
    if (m0 >= cnt) return;
    const int n0   = blockIdx.x * 256;

    const __half* W  = Wbase    + (size_t)e * K * N;
    const float*  bv = BiasBase + (size_t)e * N;

    int* s_entry = (int*)smem;
    const uint32_t sbase = (uint32_t)__cvta_generic_to_shared(smem);

    const int tid = threadIdx.x;
    if (tid < 128) {
        int idx = m0 + tid;
        s_entry[tid] = (idx < cnt) ? g_list[e * NTOK + idx] : -1;
    }
    __syncthreads();

    // ---- producer mappings ----
    const int arow_i = (tid >> 1) & 127;
    const __half* a_src;
    {
        int en = s_entry[arow_i];
        const __half* base = FC1 ? g_Xh : g_Hh;
        size_t stride      = FC1 ? D_MODEL : EXPERT_DIM;
        size_t row         = (en >= 0) ? (size_t)(FC1 ? (en >> 1) : en) : 0;
        a_src = base + row * stride + koff + (tid & 1) * 8;
    }
    const uint32_t a_dst0 = sbase + SM_A + arow_i * ASTRB + (tid & 1) * 16;
    const int bkr = tid >> 5;
    const __half* b_src = W + (size_t)(koff + bkr) * N + n0 + (tid & 31) * 8;
    const uint32_t b_dst0 = sbase + SM_B + bkr * BSTRB + (tid & 31) * 16;

    auto produce = [&](int c) {
        int s  = c % STG;
        int k0 = c * 16;
        if (tid < 256) cpa16(a_dst0 + s * SM_ASTG, a_src + k0);
        cpa16(b_dst0 + s * SM_BSTG, b_src + (size_t)k0 * N);
    };

    // ---- consumer mappings: 16 warps = 4m x 4n, warp tile 32x64 ----
    const int lane = tid & 31;
    const int wid  = tid >> 5;
    const int m0w  = (wid & 3) * 32;
    const int n0w  = (wid >> 2) * 64;
    const int qr   = lane >> 2;
    const int qc   = lane & 3;
    const int l16  = lane & 15;
    const int lhi  = lane >> 4;

    float acc[2][8][4];
    #pragma unroll
    for (int mi = 0; mi < 2; mi++)
        #pragma unroll
        for (int ni = 0; ni < 8; ni++)
            #pragma unroll
            for (int j = 0; j < 4; j++) acc[mi][ni][j] = 0.f;

    const int nst = KS / 16;

    produce(0); CPA_COMMIT();
    produce(1); CPA_COMMIT();
    produce(2); CPA_COMMIT();
    produce(3); CPA_COMMIT();

    for (int c = 0; c < nst; c++) {
        CPA_WAIT(3);
        __syncthreads();

        const uint32_t abase = sbase + SM_A + (c % STG) * SM_ASTG;
        const uint32_t bbase = sbase + SM_B + (c % STG) * SM_BSTG;

        uint32_t af[2][4];
        #pragma unroll
        for (int mi = 0; mi < 2; mi++)
            ldsm4(af[mi], abase + (m0w + mi * 16 + l16) * ASTRB + lhi * 16);
        uint32_t bf[8][2];
        #pragma unroll
        for (int np = 0; np < 4; np++) {
            uint32_t r[4];
            ldsm4t(r, bbase + l16 * BSTRB + (n0w + np * 16 + lhi * 8) * 2);
            bf[np * 2 + 0][0] = r[0]; bf[np * 2 + 0][1] = r[1];
            bf[np * 2 + 1][0] = r[2]; bf[np * 2 + 1][1] = r[3];
        }

        if (c + 4 < nst) produce(c + 4);
        CPA_COMMIT();

        #pragma unroll
        for (int mi = 0; mi < 2; mi++)
            #pragma unroll
            for (int ni = 0; ni < 8; ni++)
                mma_f16(acc[mi][ni], af[mi], bf[ni]);
    }

    // ---- epilogue ----
    #pragma unroll
    for (int mi = 0; mi < 2; mi++) {
        int r0 = m0w + mi * 16 + qr;
        int r1 = r0 + 8;
        int e0 = s_entry[r0];
        int e1 = s_entry[r1];
        #pragma unroll
        for (int ni = 0; ni < 8; ni++) {
            int ncol = n0 + n0w + ni * 8 + qc * 2;
            float bx, by;
            if (KSPLIT > 1 && ks != 0) { bx = 0.f; by = 0.f; }
            else { bx = bv[ncol]; by = bv[ncol + 1]; }
            if (FC1) {
                if (e0 >= 0) {
                    float v0 = acc[mi][ni][0] + bx;
                    float v1 = acc[mi][ni][1] + by;
                    v0 = v0 > 0.f ? v0 : 0.f;
                    v1 = v1 > 0.f ? v1 : 0.f;
                    *(__half2*)(g_Hh + (size_t)e0 * EXPERT_DIM + ncol) =
                        __floats2half2_rn(v0, v1);
                }
                if (e1 >= 0) {
                    float v0 = acc[mi][ni][2] + bx;
                    float v1 = acc[mi][ni][3] + by;
                    v0 = v0 > 0.f ? v0 : 0.f;
                    v1 = v1 > 0.f ? v1 : 0.f;
                    *(__half2*)(g_Hh + (size_t)e1 * EXPERT_DIM + ncol) =
                        __floats2half2_rn(v0, v1);
                }
            } else {
                if (e0 >= 0) {
                    float w = g_rw[e0];
                    float* p = out + (size_t)(e0 >> 1) * D_MODEL + ncol;
                    atomicAdd(p,     w * (acc[mi][ni][0] + bx));
                    atomicAdd(p + 1, w * (acc[mi][ni][1] + by));
                }
                if (e1 >= 0) {
                    float w = g_rw[e1];
                    float* p = out + (size_t)(e1 >> 1) * D_MODEL + ncol;
                    atomicAdd(p,     w * (acc[mi][ni][2] + bx));
                    atomicAdd(p + 1, w * (acc[mi][ni][3] + by));
                }
            }
        }
    }
}

extern "C" void kernel_launch(void* const* d_in, const int* in_sizes, int n_in,
                              void* d_out, int out_size) {
    (void)in_sizes; (void)n_in; (void)out_size;
    const float* x    = (const float*)d_in[0];
    const float* Wg   = (const float*)d_in[1];
    const float* bg   = (const float*)d_in[2];
    const float* bias = (const float*)d_in[3];
    const float* W1   = (const float*)d_in[4];
    const float* b1   = (const float*)d_in[5];
    const float* W2   = (const float*)d_in[6];
    const float* b2   = (const float*)d_in[7];
    float* out = (float*)d_out;

    static int init_done = 0;
    static cudaStream_t s1;
    static cudaEvent_t evFork, ev1, ev2;
    if (!init_done) {
        cudaFuncSetAttribute(expert_mma<D_MODEL, EXPERT_DIM, 1, true>,
                             cudaFuncAttributeMaxDynamicSharedMemorySize, SM_TOTAL);
        cudaFuncSetAttribute(expert_mma<EXPERT_DIM, D_MODEL, 2, false>,
                             cudaFuncAttributeMaxDynamicSharedMemorySize, SM_TOTAL);
        cudaStreamCreateWithFlags(&s1, cudaStreamNonBlocking);
        cudaEventCreateWithFlags(&evFork, cudaEventDisableTiming);
        cudaEventCreateWithFlags(&ev1,    cudaEventDisableTiming);
        cudaEventCreateWithFlags(&ev2,    cudaEventDisableTiming);
        init_done = 1;
    }

    __half *w1h, *w2h;
    cudaGetSymbolAddress((void**)&w1h, g_W1h);
    cudaGetSymbolAddress((void**)&w2h, g_W2h);

    int n4  = NTOK * D_MODEL / 4;
    int n8x = NTOK * D_MODEL / 8;
    int n8w = NUM_EXPERTS * D_MODEL * EXPERT_DIM / 8;

    // Fork side stream s1 off the capture (default) stream for weight cvt.
    cudaEventRecord(evFork, 0);
    cudaStreamWaitEvent(s1, evFork, 0);

    // s1: W1 cvt -> ev1, W2 cvt -> ev2 (overlaps gate + FC1 on s0)
    cvt_w_kernel<<<(n8w + 255) / 256, 256, 0, s1>>>(W1, w1h, n8w);
    cudaEventRecord(ev1, s1);
    cvt_w_kernel<<<(n8w + 255) / 256, 256, 0, s1>>>(W2, w2h, n8w);
    cudaEventRecord(ev2, s1);

    // s0 (default): prep_misc -> gate -> [ev1] FC1 -> [ev2] FC2
    prep_misc_kernel<<<(n4 + 255) / 256, 256>>>(x, (float4*)out, n4, n8x);
    gate_kernel<<<NTOK / 8, 256>>>(x, Wg, bg, bias);

    cudaStreamWaitEvent(0, ev1, 0);
    expert_mma<D_MODEL, EXPERT_DIM, 1, true >
        <<<dim3(EXPERT_DIM / 256, NTOK / 128, NUM_EXPERTS), 512, SM_TOTAL>>>(w1h, b1, out);

    cudaStreamWaitEvent(0, ev2, 0);
    expert_mma<EXPERT_DIM, D_MODEL, 2, false>
        <<<dim3(D_MODEL / 256,  NTOK / 128, NUM_EXPERTS * 2), 512, SM_TOTAL>>>(w2h, b2, out);
}

// round 17
// speedup vs baseline: 1.4365x; 1.4365x over previous
#include <cuda_runtime.h>
#include <cuda_fp16.h>
#include <stdint.h>
#include <math.h>

#define D_MODEL     1024
#define EXPERT_DIM  2048
#define NUM_EXPERTS 16
#define SEQ_LEN     2048
#define BATCH       2
#define NTOK        (SEQ_LEN*BATCH)      // 4096 tokens
#define NASSIGN     (NTOK*2)             // 8192 (token, k) assignments

// ---- scratch (static __device__: no allocations allowed) ----
__device__ __half g_Xh[(size_t)NTOK * D_MODEL];                        // 8 MB
__device__ __half g_Hh[(size_t)NASSIGN * EXPERT_DIM];                  // 32 MB
__device__ __half g_W1h[(size_t)NUM_EXPERTS * D_MODEL * EXPERT_DIM];   // 64 MB
__device__ __half g_W2h[(size_t)NUM_EXPERTS * EXPERT_DIM * D_MODEL];   // 64 MB
__device__ int   g_cnt[NUM_EXPERTS];
__device__ int   g_list[NUM_EXPERTS * NTOK];
__device__ float g_rw[NASSIGN];

// ---- prep_misc: zero out, zero counters, cvt x -> fp16 ----
__global__ void prep_misc_kernel(const float* __restrict__ x,
                                 float4* __restrict__ out, int n4, int n8x) {
    int i = blockIdx.x * blockDim.x + threadIdx.x;
    if (i < n4) out[i] = make_float4(0.f, 0.f, 0.f, 0.f);
    if (i < n8x) {
        const float4* in4 = (const float4*)x;
        float4 a = in4[2 * i], b = in4[2 * i + 1];
        __half2 h[4];
        h[0] = __floats2half2_rn(a.x, a.y);
        h[1] = __floats2half2_rn(a.z, a.w);
        h[2] = __floats2half2_rn(b.x, b.y);
        h[3] = __floats2half2_rn(b.z, b.w);
        *(uint4*)(g_Xh + 8 * (size_t)i) = *(uint4*)h;
    }
    if (i < NUM_EXPERTS) g_cnt[i] = 0;
}

// ---- prep_w: cvt W1 and W2 -> fp16 (one launch) ----
__global__ void prep_w_kernel(const float* __restrict__ W1,
                              const float* __restrict__ W2, int n8w) {
    int i = blockIdx.x * blockDim.x + threadIdx.x;
    if (i >= n8w) return;
    {
        const float4* in4 = (const float4*)W1;
        float4 a = in4[2 * i], b = in4[2 * i + 1];
        __half2 h[4];
        h[0] = __floats2half2_rn(a.x, a.y);
        h[1] = __floats2half2_rn(a.z, a.w);
        h[2] = __floats2half2_rn(b.x, b.y);
        h[3] = __floats2half2_rn(b.z, b.w);
        *(uint4*)(g_W1h + 8 * (size_t)i) = *(uint4*)h;
    }
    {
        const float4* in4 = (const float4*)W2;
        float4 a = in4[2 * i], b = in4[2 * i + 1];
        __half2 h[4];
        h[0] = __floats2half2_rn(a.x, a.y);
        h[1] = __floats2half2_rn(a.z, a.w);
        h[2] = __floats2half2_rn(b.x, b.y);
        h[3] = __floats2half2_rn(b.z, b.w);
        *(uint4*)(g_W2h + 8 * (size_t)i) = *(uint4*)h;
    }
}

// ---- gating: one warp per token, lane-per-expert (coalesced Wg) ----
// lane l computes expert (l & 15) over K-half (l >> 4):
//   Wg[i*16 + e] -> 16 lanes read 16 consecutive floats (one 64B sector)
//   xs[i] -> 2-way smem broadcast. Wg (64 KB) stays L1-resident.
__global__ void gate_kernel(const float* __restrict__ x,
                            const float* __restrict__ Wg,
                            const float* __restrict__ bg,
                            const float* __restrict__ bias) {
    __shared__ float xs[8][1024];
    const int wwarp = threadIdx.x >> 5;
    const int lane  = threadIdx.x & 31;
    const int token = blockIdx.x * 8 + wwarp;
    const float* xr = x + (size_t)token * D_MODEL;

    // stage x row into smem, coalesced (128 floats per iter)
    #pragma unroll
    for (int j = 0; j < 8; j++)
        *(float4*)&xs[wwarp][j * 128 + lane * 4] =
            *(const float4*)(xr + j * 128 + lane * 4);
    __syncwarp();

    const int e    = lane & 15;
    const int half = lane >> 4;
    const float* xsh = xs[wwarp] + half * 512;
    const float* wgh = Wg + (size_t)half * 512 * NUM_EXPERTS + e;

    float s = 0.f;
    #pragma unroll 8
    for (int i = 0; i < 512; i++)
        s += xsh[i] * wgh[(size_t)i * NUM_EXPERTS];
    s += __shfl_xor_sync(0xffffffffu, s, 16);

    // gather all 16 logits to every lane (warp-collective shfls)
    float logits[NUM_EXPERTS];
    #pragma unroll
    for (int k = 0; k < NUM_EXPERTS; k++)
        logits[k] = __shfl_sync(0xffffffffu, s, k) + bg[k] + bias[k];

    if (lane == 0) {
        int e0 = 0; float v0 = logits[0];
        #pragma unroll
        for (int k = 1; k < NUM_EXPERTS; k++)
            if (logits[k] > v0) { v0 = logits[k]; e0 = k; }
        int e1 = -1; float v1 = -1e30f;
        #pragma unroll
        for (int k = 0; k < NUM_EXPERTS; k++)
            if (k != e0 && logits[k] > v1) { v1 = logits[k]; e1 = k; }

        float ew1 = __expf(v1 - v0);
        float inv = 1.f / (1.f + ew1);
        g_rw[token * 2 + 0] = inv;
        g_rw[token * 2 + 1] = ew1 * inv;
        int p0 = atomicAdd(&g_cnt[e0], 1);
        g_list[e0 * NTOK + p0] = token * 2 + 0;
        int p1 = atomicAdd(&g_cnt[e1], 1);
        g_list[e1 * NTOK + p1] = token * 2 + 1;
    }
}

// ================= mma / ldmatrix / cp.async helpers =================
__device__ __forceinline__ void mma_f16(float* d, const uint32_t* a, const uint32_t* b) {
    asm volatile(
        "mma.sync.aligned.m16n8k16.row.col.f32.f16.f16.f32 "
        "{%0,%1,%2,%3}, {%4,%5,%6,%7}, {%8,%9}, {%0,%1,%2,%3};\n"
        : "+f"(d[0]), "+f"(d[1]), "+f"(d[2]), "+f"(d[3])
        : "r"(a[0]), "r"(a[1]), "r"(a[2]), "r"(a[3]), "r"(b[0]), "r"(b[1]));
}
__device__ __forceinline__ void ldsm4(uint32_t* r, uint32_t a) {
    asm volatile("ldmatrix.sync.aligned.m8n8.x4.shared.b16 {%0,%1,%2,%3}, [%4];"
        : "=r"(r[0]), "=r"(r[1]), "=r"(r[2]), "=r"(r[3]) : "r"(a));
}
__device__ __forceinline__ void ldsm4t(uint32_t* r, uint32_t a) {
    asm volatile("ldmatrix.sync.aligned.m8n8.x4.trans.shared.b16 {%0,%1,%2,%3}, [%4];"
        : "=r"(r[0]), "=r"(r[1]), "=r"(r[2]), "=r"(r[3]) : "r"(a));
}
__device__ __forceinline__ void cpa16(uint32_t dst, const void* src) {
    asm volatile("cp.async.cg.shared.global [%0], [%1], 16;" :: "r"(dst), "l"(src));
}
#define CPA_COMMIT() asm volatile("cp.async.commit_group;" ::: "memory")
#define CPA_WAIT(n)  asm volatile("cp.async.wait_group %0;" :: "n"(n) : "memory")

// smem layout (5-stage ring, k16/stage, block tile 128m x 256n, fp16):
#define ASTRB     48
#define BSTRB     528
#define STG       5
#define SM_A      512
#define SM_ASTG   (128 * ASTRB)              // 6144
#define SM_B      (SM_A + STG * SM_ASTG)     // 31232
#define SM_BSTG   (16 * BSTRB)               // 8448
#define SM_TOTAL  (SM_B + STG * SM_BSTG)     // 73472

// 512 threads = 16 warps (4m x 4n), warp tile 32x64, 1 CTA/SM. (round-8 proven)
template<int K, int N, int KSPLIT, bool FC1>
__global__ __launch_bounds__(512, 1)
void expert_mma(const __half* __restrict__ Wbase,
                const float* __restrict__ BiasBase,
                float* __restrict__ out) {
    extern __shared__ char smem[];
    const int z    = blockIdx.z;
    const int e    = z / KSPLIT;
    const int ks   = z % KSPLIT;
    const int KS   = K / KSPLIT;
    const int koff = ks * KS;
    const int cnt  = g_cnt[e];
    const int m0   = blockIdx.y * 128;
    if (m0 >= cnt) return;
    const int n0   = blockIdx.x * 256;

    const __half* W  = Wbase    + (size_t)e * K * N;
    const float*  bv = BiasBase + (size_t)e * N;

    int* s_entry = (int*)smem;
    const uint32_t sbase = (uint32_t)__cvta_generic_to_shared(smem);

    const int tid = threadIdx.x;
    if (tid < 128) {
        int idx = m0 + tid;
        s_entry[tid] = (idx < cnt) ? g_list[e * NTOK + idx] : -1;
    }
    __syncthreads();

    // ---- producer mappings ----
    const int arow_i = (tid >> 1) & 127;
    const __half* a_src;
    {
        int en = s_entry[arow_i];
        const __half* base = FC1 ? g_Xh : g_Hh;
        size_t stride      = FC1 ? D_MODEL : EXPERT_DIM;
        size_t row         = (en >= 0) ? (size_t)(FC1 ? (en >> 1) : en) : 0;
        a_src = base + row * stride + koff + (tid & 1) * 8;
    }
    const uint32_t a_dst0 = sbase + SM_A + arow_i * ASTRB + (tid & 1) * 16;
    const int bkr = tid >> 5;
    const __half* b_src = W + (size_t)(koff + bkr) * N + n0 + (tid & 31) * 8;
    const uint32_t b_dst0 = sbase + SM_B + bkr * BSTRB + (tid & 31) * 16;

    auto produce = [&](int c) {
        int s  = c % STG;
        int k0 = c * 16;
        if (tid < 256) cpa16(a_dst0 + s * SM_ASTG, a_src + k0);
        cpa16(b_dst0 + s * SM_BSTG, b_src + (size_t)k0 * N);
    };

    // ---- consumer mappings: 16 warps = 4m x 4n, warp tile 32x64 ----
    const int lane = tid & 31;
    const int wid  = tid >> 5;
    const int m0w  = (wid & 3) * 32;
    const int n0w  = (wid >> 2) * 64;
    const int qr   = lane >> 2;
    const int qc   = lane & 3;
    const int l16  = lane & 15;
    const int lhi  = lane >> 4;

    float acc[2][8][4];
    #pragma unroll
    for (int mi = 0; mi < 2; mi++)
        #pragma unroll
        for (int ni = 0; ni < 8; ni++)
            #pragma unroll
            for (int j = 0; j < 4; j++) acc[mi][ni][j] = 0.f;

    const int nst = KS / 16;

    produce(0); CPA_COMMIT();
    produce(1); CPA_COMMIT();
    produce(2); CPA_COMMIT();
    produce(3); CPA_COMMIT();

    for (int c = 0; c < nst; c++) {
        CPA_WAIT(3);
        __syncthreads();

        const uint32_t abase = sbase + SM_A + (c % STG) * SM_ASTG;
        const uint32_t bbase = sbase + SM_B + (c % STG) * SM_BSTG;

        uint32_t af[2][4];
        #pragma unroll
        for (int mi = 0; mi < 2; mi++)
            ldsm4(af[mi], abase + (m0w + mi * 16 + l16) * ASTRB + lhi * 16);
        uint32_t bf[8][2];
        #pragma unroll
        for (int np = 0; np < 4; np++) {
            uint32_t r[4];
            ldsm4t(r, bbase + l16 * BSTRB + (n0w + np * 16 + lhi * 8) * 2);
            bf[np * 2 + 0][0] = r[0]; bf[np * 2 + 0][1] = r[1];
            bf[np * 2 + 1][0] = r[2]; bf[np * 2 + 1][1] = r[3];
        }

        if (c + 4 < nst) produce(c + 4);
        CPA_COMMIT();

        #pragma unroll
        for (int mi = 0; mi < 2; mi++)
            #pragma unroll
            for (int ni = 0; ni < 8; ni++)
                mma_f16(acc[mi][ni], af[mi], bf[ni]);
    }

    // ---- epilogue ----
    #pragma unroll
    for (int mi = 0; mi < 2; mi++) {
        int r0 = m0w + mi * 16 + qr;
        int r1 = r0 + 8;
        int e0 = s_entry[r0];
        int e1 = s_entry[r1];
        #pragma unroll
        for (int ni = 0; ni < 8; ni++) {
            int ncol = n0 + n0w + ni * 8 + qc * 2;
            float bx, by;
            if (KSPLIT > 1 && ks != 0) { bx = 0.f; by = 0.f; }
            else { bx = bv[ncol]; by = bv[ncol + 1]; }
            if (FC1) {
                if (e0 >= 0) {
                    float v0 = acc[mi][ni][0] + bx;
                    float v1 = acc[mi][ni][1] + by;
                    v0 = v0 > 0.f ? v0 : 0.f;
                    v1 = v1 > 0.f ? v1 : 0.f;
                    *(__half2*)(g_Hh + (size_t)e0 * EXPERT_DIM + ncol) =
                        __floats2half2_rn(v0, v1);
                }
                if (e1 >= 0) {
                    float v0 = acc[mi][ni][2] + bx;
                    float v1 = acc[mi][ni][3] + by;
                    v0 = v0 > 0.f ? v0 : 0.f;
                    v1 = v1 > 0.f ? v1 : 0.f;
                    *(__half2*)(g_Hh + (size_t)e1 * EXPERT_DIM + ncol) =
                        __floats2half2_rn(v0, v1);
                }
            } else {
                if (e0 >= 0) {
                    float w = g_rw[e0];
                    float* p = out + (size_t)(e0 >> 1) * D_MODEL + ncol;
                    atomicAdd(p,     w * (acc[mi][ni][0] + bx));
                    atomicAdd(p + 1, w * (acc[mi][ni][1] + by));
                }
                if (e1 >= 0) {
                    float w = g_rw[e1];
                    float* p = out + (size_t)(e1 >> 1) * D_MODEL + ncol;
                    atomicAdd(p,     w * (acc[mi][ni][2] + bx));
                    atomicAdd(p + 1, w * (acc[mi][ni][3] + by));
                }
            }
        }
    }
}

extern "C" void kernel_launch(void* const* d_in, const int* in_sizes, int n_in,
                              void* d_out, int out_size) {
    (void)in_sizes; (void)n_in; (void)out_size;
    const float* x    = (const float*)d_in[0];
    const float* Wg   = (const float*)d_in[1];
    const float* bg   = (const float*)d_in[2];
    const float* bias = (const float*)d_in[3];
    const float* W1   = (const float*)d_in[4];
    const float* b1   = (const float*)d_in[5];
    const float* W2   = (const float*)d_in[6];
    const float* b2   = (const float*)d_in[7];
    float* out = (float*)d_out;

    static int attr_done = 0;
    if (!attr_done) {
        cudaFuncSetAttribute(expert_mma<D_MODEL, EXPERT_DIM, 1, true>,
                             cudaFuncAttributeMaxDynamicSharedMemorySize, SM_TOTAL);
        cudaFuncSetAttribute(expert_mma<EXPERT_DIM, D_MODEL, 2, false>,
                             cudaFuncAttributeMaxDynamicSharedMemorySize, SM_TOTAL);
        attr_done = 1;
    }

    __half *w1h, *w2h;
    cudaGetSymbolAddress((void**)&w1h, g_W1h);
    cudaGetSymbolAddress((void**)&w2h, g_W2h);

    int n4  = NTOK * D_MODEL / 4;
    int n8x = NTOK * D_MODEL / 8;
    int n8w = NUM_EXPERTS * D_MODEL * EXPERT_DIM / 8;

    // serial pipeline (proven); FC1 is launch #4 (ncu profiles launch #4)
    prep_misc_kernel<<<(n4 + 255) / 256, 256>>>(x, (float4*)out, n4, n8x);       // 1
    gate_kernel<<<NTOK / 8, 256>>>(x, Wg, bg, bias);                             // 2
    prep_w_kernel<<<(n8w + 255) / 256, 256>>>(W1, W2, n8w);                      // 3
    expert_mma<D_MODEL, EXPERT_DIM, 1, true >                                    // 4 (profiled)
        <<<dim3(EXPERT_DIM / 256, NTOK / 128, NUM_EXPERTS), 512, SM_TOTAL>>>(w1h, b1, out);
    expert_mma<EXPERT_DIM, D_MODEL, 2, false>                                    // 5
        <<<dim3(D_MODEL / 256,  NTOK / 128, NUM_EXPERTS * 2), 512, SM_TOTAL>>>(w2h, b2, out);
}